// round 3
// baseline (speedup 1.0000x reference)
#include <cuda_runtime.h>

#define NSRC 100000
#define NTGT 100000
#define NEDGE 1600000
#define FDIM 64
#define NLAYER 3

// ---------------- scratch (device globals; no allocations allowed) ----------
__device__ float g_xs[2][(size_t)NSRC * FDIM];
__device__ float g_xt[2][(size_t)NTGT * FDIM];
__device__ float g_agg_s[(size_t)NSRC * FDIM];
__device__ float g_agg_t[(size_t)NTGT * FDIM];
__device__ float g_inv_s[NSRC];
__device__ float g_inv_t[NTGT];
__device__ int   g_deg_s[NSRC];
__device__ int   g_deg_t[NTGT];
__device__ float g_sum;

// ---------------- degree computation (layer-invariant, done once) ------------
__global__ void deg_kernel(const int* __restrict__ ei_s2t,
                           const int* __restrict__ ei_t2s) {
    int i = blockIdx.x * blockDim.x + threadIdx.x;
    if (i < NEDGE) {
        atomicAdd(&g_deg_t[ei_s2t[NEDGE + i]], 1);
    } else if (i < 2 * NEDGE) {
        atomicAdd(&g_deg_s[ei_t2s[i]], 1);   // i in [NEDGE, 2*NEDGE) -> dst row
    }
}

__global__ void inv_kernel() {
    int i = blockIdx.x * blockDim.x + threadIdx.x;
    if (i < NSRC) g_inv_s[i] = 1.0f / (float)max(g_deg_s[i], 1);
    if (i < NTGT) g_inv_t[i] = 1.0f / (float)max(g_deg_t[i], 1);
}

// ---------------- edge scatter: 16 threads per edge, float4 gather + v4 red --
__global__ void scatter_kernel(const float4* __restrict__ src_feat,
                               float4* __restrict__ agg,
                               const int* __restrict__ ei) {
    unsigned g = blockIdx.x * blockDim.x + threadIdx.x;
    unsigned e = g >> 4;
    unsigned lane = g & 15;
    if (e >= NEDGE) return;
    int s = __ldg(ei + e);
    int d = __ldg(ei + NEDGE + e);
    float4 v = __ldg(src_feat + (size_t)s * 16 + lane);
    float4* p = agg + (size_t)d * 16 + lane;
    asm volatile("red.global.v4.f32.add [%0], {%1, %2, %3, %4};"
                 :: "l"(p), "f"(v.x), "f"(v.y), "f"(v.z), "f"(v.w)
                 : "memory");
}

// ---------------- fused SAGE transform: out = [agg*inv | x] @ [Wl|Wr]^T + b --
// Block: 256 threads, tile 64 nodes x 64 outputs, 4x4 register microtile.
#define WPITCH 66  // pad to 66 floats to break bank conflicts on transpose store
#define COMBINE_SMEM (128 * WPITCH * 4 + 64 * 128 * 4)

__global__ void combine_kernel(const float* __restrict__ agg,
                               const float* __restrict__ inv,
                               const float* __restrict__ xdst,
                               const float* __restrict__ Wl,
                               const float* __restrict__ Wr,
                               const float* __restrict__ bias,
                               float* __restrict__ out, int n) {
    extern __shared__ float sm[];
    float* Wt = sm;                  // [128][WPITCH]  Wt[k][o] = Wcat[o][k]
    float* Vs = sm + 128 * WPITCH;   // [64][128]      Vs[n][k] = [agg*inv | x]
    int tid = threadIdx.x;

    // Load weights (transposed into shared). Wl/Wr are [64 out][64 in] row-major.
    #pragma unroll
    for (int j = 0; j < 16; j++) {
        int idx = tid + 256 * j;          // 0..4095
        int o = idx >> 6, f = idx & 63;
        float wl = Wl[idx];
        float wr = Wr[idx];
        Wt[f * WPITCH + o] = wl;
        Wt[(64 + f) * WPITCH + o] = wr;
    }

    int base = blockIdx.x * 64;
    // Load V tile: 64 nodes x 128 features (zero-padded past n)
    #pragma unroll
    for (int j = 0; j < 32; j++) {
        int idx = tid + 256 * j;          // 0..8191
        int nn = idx >> 7, k = idx & 127;
        int node = base + nn;
        float v = 0.0f;
        if (node < n) {
            v = (k < 64) ? agg[(size_t)node * 64 + k] * inv[node]
                         : xdst[(size_t)node * 64 + (k - 64)];
        }
        Vs[idx] = v;
    }
    __syncthreads();

    int ob = tid & 15;           // output cols: ob + 16*j  (strided -> no conflicts)
    int nb = (tid >> 4) * 4;     // node rows:  nb .. nb+3

    float acc[4][4];
    #pragma unroll
    for (int i = 0; i < 4; i++)
        #pragma unroll
        for (int j = 0; j < 4; j++)
            acc[i][j] = bias[ob + 16 * j];

    #pragma unroll 4
    for (int k = 0; k < 128; k++) {
        float w0 = Wt[k * WPITCH + ob];
        float w1 = Wt[k * WPITCH + ob + 16];
        float w2 = Wt[k * WPITCH + ob + 32];
        float w3 = Wt[k * WPITCH + ob + 48];
        #pragma unroll
        for (int i = 0; i < 4; i++) {
            float v = Vs[(nb + i) * 128 + k];
            acc[i][0] += v * w0;
            acc[i][1] += v * w1;
            acc[i][2] += v * w2;
            acc[i][3] += v * w3;
        }
    }

    #pragma unroll
    for (int i = 0; i < 4; i++) {
        int node = base + nb + i;
        if (node < n) {
            #pragma unroll
            for (int j = 0; j < 4; j++)
                out[(size_t)node * 64 + ob + 16 * j] = acc[i][j];
        }
    }
}

// ---------------- fused global mean pool + final linear ---------------------
__global__ void reduce_kernel(const float* __restrict__ xs,
                              const float* __restrict__ xt,
                              const float* __restrict__ w) {
    __shared__ float ws[64];
    __shared__ float partial[8];
    int tid = threadIdx.x;
    if (tid < 64) ws[tid] = w[tid];
    __syncthreads();

    int i = blockIdx.x * blockDim.x + tid;
    float acc = 0.0f;
    if (i < NSRC + NTGT) {
        const float4* x = (const float4*)((i < NSRC)
                            ? xs + (size_t)i * 64
                            : xt + (size_t)(i - NSRC) * 64);
        #pragma unroll
        for (int j = 0; j < 16; j++) {
            float4 v = __ldg(x + j);
            acc += v.x * ws[4 * j] + v.y * ws[4 * j + 1] +
                   v.z * ws[4 * j + 2] + v.w * ws[4 * j + 3];
        }
    }
    #pragma unroll
    for (int off = 16; off; off >>= 1)
        acc += __shfl_down_sync(0xffffffffu, acc, off);
    if ((tid & 31) == 0) partial[tid >> 5] = acc;
    __syncthreads();
    if (tid < 8) {
        float v = partial[tid];
        #pragma unroll
        for (int off = 4; off; off >>= 1)
            v += __shfl_down_sync(0xffu, v, off);
        if (tid == 0) atomicAdd(&g_sum, v);
    }
}

__global__ void finalize_kernel(const float* __restrict__ lin_b,
                                float* __restrict__ out) {
    out[0] = g_sum * (1.0f / (float)(NSRC + NTGT)) + lin_b[0];
}

// ---------------- launch --------------------------------------------------
extern "C" void kernel_launch(void* const* d_in, const int* in_sizes, int n_in,
                              void* d_out, int out_size) {
    const float* x_source = (const float*)d_in[0];
    const float* x_target = (const float*)d_in[1];
    // d_in[2], d_in[3]: edge_attr (unused by the reference path)
    const float* W_l_s2t = (const float*)d_in[4];
    const float* b_s2t   = (const float*)d_in[5];
    const float* W_r_s2t = (const float*)d_in[6];
    const float* W_l_t2s = (const float*)d_in[7];
    const float* b_t2s   = (const float*)d_in[8];
    const float* W_r_t2s = (const float*)d_in[9];
    const float* lin_W   = (const float*)d_in[10];
    const float* lin_b   = (const float*)d_in[11];
    const int* ei_s2t    = (const int*)d_in[12];
    const int* ei_t2s    = (const int*)d_in[13];
    float* out = (float*)d_out;

    float *xs_buf, *xt_buf, *agg_s, *agg_t, *sum_p, *inv_s, *inv_t;
    int *deg_s, *deg_t;
    cudaGetSymbolAddress((void**)&xs_buf, g_xs);
    cudaGetSymbolAddress((void**)&xt_buf, g_xt);
    cudaGetSymbolAddress((void**)&agg_s, g_agg_s);
    cudaGetSymbolAddress((void**)&agg_t, g_agg_t);
    cudaGetSymbolAddress((void**)&deg_s, g_deg_s);
    cudaGetSymbolAddress((void**)&deg_t, g_deg_t);
    cudaGetSymbolAddress((void**)&sum_p, g_sum);
    cudaGetSymbolAddress((void**)&inv_s, g_inv_s);   // FIX: device addr, not
    cudaGetSymbolAddress((void**)&inv_t, g_inv_t);   // host shadow symbol

    float* xs0 = xs_buf;
    float* xs1 = xs_buf + (size_t)NSRC * FDIM;
    float* xt0 = xt_buf;
    float* xt1 = xt_buf + (size_t)NTGT * FDIM;

    cudaFuncSetAttribute(combine_kernel,
                         cudaFuncAttributeMaxDynamicSharedMemorySize,
                         COMBINE_SMEM);

    // Degrees (layer-invariant)
    cudaMemsetAsync(deg_s, 0, NSRC * sizeof(int));
    cudaMemsetAsync(deg_t, 0, NTGT * sizeof(int));
    deg_kernel<<<(2 * NEDGE + 255) / 256, 256>>>(ei_s2t, ei_t2s);
    inv_kernel<<<(NSRC + 255) / 256, 256>>>();

    const float* cxs = x_source;
    const float* cxt = x_target;

    const unsigned scatter_grid = ((unsigned)NEDGE * 16 + 255) / 256;
    const int combine_grid_t = (NTGT + 63) / 64;
    const int combine_grid_s = (NSRC + 63) / 64;

    for (int l = 0; l < NLAYER; l++) {
        cudaMemsetAsync(agg_t, 0, (size_t)NTGT * FDIM * sizeof(float));
        cudaMemsetAsync(agg_s, 0, (size_t)NSRC * FDIM * sizeof(float));

        scatter_kernel<<<scatter_grid, 256>>>((const float4*)cxs,
                                              (float4*)agg_t, ei_s2t);
        scatter_kernel<<<scatter_grid, 256>>>((const float4*)cxt,
                                              (float4*)agg_s, ei_t2s);

        float* oxt = (l == 1) ? xt1 : xt0;
        float* oxs = (l == 1) ? xs1 : xs0;

        combine_kernel<<<combine_grid_t, 256, COMBINE_SMEM>>>(
            agg_t, inv_t, cxt,
            W_l_s2t + (size_t)l * 64 * 64, W_r_s2t + (size_t)l * 64 * 64,
            b_s2t + (size_t)l * 64, oxt, NTGT);
        combine_kernel<<<combine_grid_s, 256, COMBINE_SMEM>>>(
            agg_s, inv_s, cxs,
            W_l_t2s + (size_t)l * 64 * 64, W_r_t2s + (size_t)l * 64 * 64,
            b_t2s + (size_t)l * 64, oxs, NSRC);

        cxs = oxs;
        cxt = oxt;
    }

    cudaMemsetAsync(sum_p, 0, sizeof(float));
    reduce_kernel<<<(NSRC + NTGT + 255) / 256, 256>>>(cxs, cxt, lin_W);
    finalize_kernel<<<1, 1>>>(lin_b, out);
}

// round 4
// speedup vs baseline: 6.8714x; 6.8714x over previous
#include <cuda_runtime.h>

#define NSRC 100000
#define NTGT 100000
#define NEDGE 1600000
#define NTOT (NSRC + NTGT)

// ---------------- scratch (device globals; no allocations) ------------------
__device__ int   g_deg_s[NSRC];
__device__ int   g_deg_t[NTGT];
__device__ float g_inv_s[NSRC];
__device__ float g_inv_t[NTGT];
__device__ float g_a[3][NSRC];   // a1, a2, a3  (S^T 1_t, S^T T^T 1_s, S^T T^T S^T 1_t)
__device__ float g_b[3][NTGT];   // b1, b2, b3  (T^T 1_s, T^T S^T 1_t, T^T S^T T^T 1_s)
__device__ float g_pa[NSRC];     // a_r * inv_s  (staging for next SpMV)
__device__ float g_pb[NTGT];     // b_r * inv_t
__device__ float g_psums[4];     // sum(a1), sum(a2), sum(b1), sum(b2)
__device__ float g_Q[8][64];     // QS[0..3], QT[0..3] at level 0
__device__ float g_acc;          // bias scalar contributions
__device__ float g_sum;          // final node-sum

// ---------------- degrees (dst in-degree per direction) ---------------------
__global__ void deg_kernel(const int* __restrict__ ei_s2t,
                           const int* __restrict__ ei_t2s) {
    int i = blockIdx.x * blockDim.x + threadIdx.x;
    if (i < NEDGE) {
        atomicAdd(&g_deg_t[ei_s2t[NEDGE + i]], 1);
    } else if (i < 2 * NEDGE) {
        atomicAdd(&g_deg_s[ei_t2s[i]], 1);   // i in [NEDGE,2E) is the dst row
    }
}

__global__ void inv_kernel() {
    int i = blockIdx.x * blockDim.x + threadIdx.x;
    if (i < NSRC) g_inv_s[i] = 1.0f / (float)max(g_deg_s[i], 1);
    if (i < NTGT) g_inv_t[i] = 1.0f / (float)max(g_deg_t[i], 1);
}

// ---------------- scalar SpMVs ----------------------------------------------
// a1[src] += inv_t[dst] over s2t ; b1[src] += inv_s[dst] over t2s
__global__ void spmv1_kernel(const int* __restrict__ s2t,
                             const int* __restrict__ t2s) {
    int i = blockIdx.x * blockDim.x + threadIdx.x;
    if (i < NEDGE) {
        atomicAdd(&g_a[0][__ldg(s2t + i)], g_inv_t[__ldg(s2t + NEDGE + i)]);
    } else if (i < 2 * NEDGE) {
        int e = i - NEDGE;
        atomicAdd(&g_b[0][__ldg(t2s + e)], g_inv_s[__ldg(t2s + NEDGE + e)]);
    }
}

// pa = a[r] * inv_s ; pb = b[r] * inv_t
__global__ void prep_kernel(int r) {
    int i = blockIdx.x * blockDim.x + threadIdx.x;
    if (i < NSRC) g_pa[i] = g_a[r][i] * g_inv_s[i];
    if (i < NTGT) g_pb[i] = g_b[r][i] * g_inv_t[i];
}

// a[r][src] += pb[dst] over s2t ; b[r][src] += pa[dst] over t2s
__global__ void spmv_next_kernel(const int* __restrict__ s2t,
                                 const int* __restrict__ t2s, int r) {
    int i = blockIdx.x * blockDim.x + threadIdx.x;
    if (i < NEDGE) {
        atomicAdd(&g_a[r][__ldg(s2t + i)], g_pb[__ldg(s2t + NEDGE + i)]);
    } else if (i < 2 * NEDGE) {
        int e = i - NEDGE;
        atomicAdd(&g_b[r][__ldg(t2s + e)], g_pa[__ldg(t2s + NEDGE + e)]);
    }
}

// sums of a1,a2,b1,b2 (needed only for bias terms; exact regardless)
__global__ void sums_kernel() {
    int i = blockIdx.x * blockDim.x + threadIdx.x;
    float v0 = 0, v1 = 0, v2 = 0, v3 = 0;
    if (i < NSRC) { v0 = g_a[0][i]; v1 = g_a[1][i]; }
    if (i < NTGT) { v2 = g_b[0][i]; v3 = g_b[1][i]; }
    #pragma unroll
    for (int off = 16; off; off >>= 1) {
        v0 += __shfl_down_sync(0xffffffffu, v0, off);
        v1 += __shfl_down_sync(0xffffffffu, v1, off);
        v2 += __shfl_down_sync(0xffffffffu, v2, off);
        v3 += __shfl_down_sync(0xffffffffu, v3, off);
    }
    if ((threadIdx.x & 31) == 0) {
        atomicAdd(&g_psums[0], v0);
        atomicAdd(&g_psums[1], v1);
        atomicAdd(&g_psums[2], v2);
        atomicAdd(&g_psums[3], v3);
    }
}

// ---------------- backward q-coefficient recursion (single block, 64 thr) ---
// Terms p^T X q with p indexed symbolically: s_k / t_k, crossing sides
// increments k (S^T / T^T). Maintain merged coefficient vectors QS[k], QT[k].
// Descend level l+1 -> l with layer-l weights:
//   nQS[k] = Wr_t2s[l]^T QS[k] + Wl_s2t[l]^T QT[k-1]
//   nQT[k] = Wr_s2t[l]^T QT[k] + Wl_t2s[l]^T QS[k-1]
//   acc   += sum_k ss[k]*(b_t2s[l].QS[k]) + st[k]*(b_s2t[l].QT[k])
__global__ void qcoef_kernel(const float* __restrict__ Wl_s2t,
                             const float* __restrict__ b_s2t,
                             const float* __restrict__ Wr_s2t,
                             const float* __restrict__ Wl_t2s,
                             const float* __restrict__ b_t2s,
                             const float* __restrict__ Wr_t2s,
                             const float* __restrict__ lin_W) {
    __shared__ float QS[4][64], QT[4][64];
    __shared__ float red[64];
    int t = threadIdx.x;  // 64 threads

    float w = lin_W[t];   // [64,1] row-major == 64 contiguous floats
    #pragma unroll
    for (int k = 0; k < 4; k++) {
        QS[k][t] = (k == 0) ? w : 0.0f;
        QT[k][t] = (k == 0) ? w : 0.0f;
    }
    __syncthreads();

    float ss[4] = {(float)NSRC, g_psums[0], g_psums[1], 0.0f};
    float st[4] = {(float)NTGT, g_psums[2], g_psums[3], 0.0f};
    float acc = 0.0f;

    for (int l = 2; l >= 0; l--) {
        const float* A  = Wl_s2t + l * 4096;  // xt <- agg(xs)
        const float* B  = Wr_s2t + l * 4096;  // xt <- xt
        const float* C  = Wl_t2s + l * 4096;  // xs <- agg(xt)
        const float* Ew = Wr_t2s + l * 4096;  // xs <- xs
        float bsv = b_t2s[l * 64 + t];
        float btv = b_s2t[l * 64 + t];

        // bias contributions from level l+1 terms
        #pragma unroll
        for (int k = 0; k < 4; k++)
            acc += ss[k] * bsv * QS[k][t] + st[k] * btv * QT[k][t];

        float rs[4] = {0, 0, 0, 0}, rt[4] = {0, 0, 0, 0};
        for (int o = 0; o < 64; o++) {
            float ev = Ew[o * 64 + t];
            float av = A[o * 64 + t];
            float bv = B[o * 64 + t];
            float cv = C[o * 64 + t];
            rs[0] += ev * QS[0][o];
            rs[1] += ev * QS[1][o] + av * QT[0][o];
            rs[2] += ev * QS[2][o] + av * QT[1][o];
            rs[3] += ev * QS[3][o] + av * QT[2][o];
            rt[0] += bv * QT[0][o];
            rt[1] += bv * QT[1][o] + cv * QS[0][o];
            rt[2] += bv * QT[2][o] + cv * QS[1][o];
            rt[3] += bv * QT[3][o] + cv * QS[2][o];
        }
        __syncthreads();
        #pragma unroll
        for (int k = 0; k < 4; k++) { QS[k][t] = rs[k]; QT[k][t] = rt[k]; }
        __syncthreads();
    }

    #pragma unroll
    for (int k = 0; k < 4; k++) {
        g_Q[k][t]     = QS[k][t];
        g_Q[4 + k][t] = QT[k][t];
    }

    // reduce acc across 64 threads
    red[t] = acc;
    __syncthreads();
    if (t == 0) {
        float s = 0;
        #pragma unroll
        for (int i = 0; i < 64; i++) s += red[i];
        g_acc = s;
    }
}

// ---------------- final evaluation over the ORIGINAL inputs -----------------
__global__ void final_kernel(const float* __restrict__ xs,
                             const float* __restrict__ xt) {
    __shared__ float Q[8 * 64];
    __shared__ float partial[8];
    int tid = threadIdx.x;
    Q[tid] = ((const float*)g_Q)[tid];
    Q[tid + 256] = ((const float*)g_Q)[tid + 256];
    __syncthreads();

    int i = blockIdx.x * blockDim.x + tid;
    float v = 0.0f;
    if (i < NTOT) {
        bool is_s = (i < NSRC);
        int n = is_s ? i : i - NSRC;
        const float4* x = (const float4*)((is_s ? xs : xt) + (size_t)n * 64);
        const float4* Q0 = (const float4*)(Q + (is_s ? 0 : 256));
        const float4* Q1 = Q0 + 16;
        const float4* Q2 = Q0 + 32;
        const float4* Q3 = Q0 + 48;
        float c1 = is_s ? g_a[0][n] : g_b[0][n];
        float c2 = is_s ? g_a[1][n] : g_b[1][n];
        float c3 = is_s ? g_a[2][n] : g_b[2][n];
        #pragma unroll
        for (int j = 0; j < 16; j++) {
            float4 xv = __ldg(x + j);
            float4 q0 = Q0[j], q1 = Q1[j], q2 = Q2[j], q3 = Q3[j];
            v += xv.x * (q0.x + c1 * q1.x + c2 * q2.x + c3 * q3.x);
            v += xv.y * (q0.y + c1 * q1.y + c2 * q2.y + c3 * q3.y);
            v += xv.z * (q0.z + c1 * q1.z + c2 * q2.z + c3 * q3.z);
            v += xv.w * (q0.w + c1 * q1.w + c2 * q2.w + c3 * q3.w);
        }
    }
    #pragma unroll
    for (int off = 16; off; off >>= 1)
        v += __shfl_down_sync(0xffffffffu, v, off);
    if ((tid & 31) == 0) partial[tid >> 5] = v;
    __syncthreads();
    if (tid < 8) {
        float p = partial[tid];
        #pragma unroll
        for (int off = 4; off; off >>= 1)
            p += __shfl_down_sync(0xffu, p, off);
        if (tid == 0) atomicAdd(&g_sum, p);
    }
}

__global__ void finalize_kernel(const float* __restrict__ lin_b,
                                float* __restrict__ out) {
    out[0] = (g_sum + g_acc) * (1.0f / (float)NTOT) + lin_b[0];
}

// ---------------- launch ----------------------------------------------------
extern "C" void kernel_launch(void* const* d_in, const int* in_sizes, int n_in,
                              void* d_out, int out_size) {
    const float* x_source = (const float*)d_in[0];
    const float* x_target = (const float*)d_in[1];
    // d_in[2], d_in[3]: edge_attr (unused by the reference path)
    const float* W_l_s2t = (const float*)d_in[4];
    const float* b_s2t   = (const float*)d_in[5];
    const float* W_r_s2t = (const float*)d_in[6];
    const float* W_l_t2s = (const float*)d_in[7];
    const float* b_t2s   = (const float*)d_in[8];
    const float* W_r_t2s = (const float*)d_in[9];
    const float* lin_W   = (const float*)d_in[10];
    const float* lin_b   = (const float*)d_in[11];
    const int* ei_s2t    = (const int*)d_in[12];
    const int* ei_t2s    = (const int*)d_in[13];
    float* out = (float*)d_out;

    // resolve ALL device globals used host-side (Round-2 lesson)
    void *deg_s, *deg_t, *a_p, *b_p, *psums_p, *sum_p;
    cudaGetSymbolAddress(&deg_s, g_deg_s);
    cudaGetSymbolAddress(&deg_t, g_deg_t);
    cudaGetSymbolAddress(&a_p, g_a);
    cudaGetSymbolAddress(&b_p, g_b);
    cudaGetSymbolAddress(&psums_p, g_psums);
    cudaGetSymbolAddress(&sum_p, g_sum);

    cudaMemsetAsync(deg_s, 0, NSRC * sizeof(int));
    cudaMemsetAsync(deg_t, 0, NTGT * sizeof(int));
    cudaMemsetAsync(a_p, 0, 3 * NSRC * sizeof(float));
    cudaMemsetAsync(b_p, 0, 3 * NTGT * sizeof(float));
    cudaMemsetAsync(psums_p, 0, 4 * sizeof(float));
    cudaMemsetAsync(sum_p, 0, sizeof(float));

    const int eg = (2 * NEDGE + 255) / 256;       // 2E edge-parallel grids
    const int ng = (NSRC + 255) / 256;

    deg_kernel<<<eg, 256>>>(ei_s2t, ei_t2s);
    inv_kernel<<<ng, 256>>>();

    spmv1_kernel<<<eg, 256>>>(ei_s2t, ei_t2s);        // a1, b1
    prep_kernel<<<ng, 256>>>(0);
    spmv_next_kernel<<<eg, 256>>>(ei_s2t, ei_t2s, 1); // a2, b2
    prep_kernel<<<ng, 256>>>(1);
    spmv_next_kernel<<<eg, 256>>>(ei_s2t, ei_t2s, 2); // a3, b3

    sums_kernel<<<ng, 256>>>();
    qcoef_kernel<<<1, 64>>>(W_l_s2t, b_s2t, W_r_s2t,
                            W_l_t2s, b_t2s, W_r_t2s, lin_W);

    final_kernel<<<(NTOT + 255) / 256, 256>>>(x_source, x_target);
    finalize_kernel<<<1, 1>>>(lin_b, out);
}

// round 5
// speedup vs baseline: 7.3136x; 1.0644x over previous
#include <cuda_runtime.h>

#define NSRC 100000
#define NTGT 100000
#define NEDGE 1600000
#define NTOT (NSRC + NTGT)
#define E4 (NEDGE / 4)

// ---------------- scratch: one contiguous zero-init block + rest ------------
struct ZeroBlock {
    int   deg_s[NSRC];
    int   deg_t[NTGT];
    float a[3][NSRC];   // a1,a2,a3 = S^T 1_t, S^T T^T 1_s, S^T T^T S^T 1_t
    float b[3][NTGT];   // b1,b2,b3 (mirror)
    float psums[4];     // sum(a1), sum(a2), sum(b1), sum(b2)
    float sum;          // final node-sum
};
__device__ ZeroBlock gz;
__device__ float g_pa[NSRC];     // a_r * inv_s (staging, fully overwritten)
__device__ float g_pb[NTGT];
__device__ float g_Q[8][64];     // level-0 coefficient vectors (fully written)
__device__ float g_acc;          // bias scalar contribution (fully written)

__device__ __forceinline__ float rcp_deg(int d) {
    return 1.0f / (float)max(d, 1);
}

// ---------------- degrees: 4 edges/thread, int4 dst loads -------------------
__global__ void deg_kernel(const int4* __restrict__ s2t_dst,
                           const int4* __restrict__ t2s_dst) {
    int i = blockIdx.x * blockDim.x + threadIdx.x;
    if (i < E4) {
        int4 d = __ldg(s2t_dst + i);
        atomicAdd(&gz.deg_t[d.x], 1);
        atomicAdd(&gz.deg_t[d.y], 1);
        atomicAdd(&gz.deg_t[d.z], 1);
        atomicAdd(&gz.deg_t[d.w], 1);
    } else if (i < 2 * E4) {
        int4 d = __ldg(t2s_dst + (i - E4));
        atomicAdd(&gz.deg_s[d.x], 1);
        atomicAdd(&gz.deg_s[d.y], 1);
        atomicAdd(&gz.deg_s[d.z], 1);
        atomicAdd(&gz.deg_s[d.w], 1);
    }
}

// ---------------- spmv1: a1[src] += rcp(deg_t[dst]) (and b1 mirror) ---------
__global__ void spmv1_kernel(const int4* __restrict__ s2t,
                             const int4* __restrict__ t2s) {
    int i = blockIdx.x * blockDim.x + threadIdx.x;
    if (i < E4) {
        int4 s = __ldg(s2t + i);
        int4 d = __ldg(s2t + E4 + i);
        float vx = rcp_deg(__ldg(&gz.deg_t[d.x]));
        float vy = rcp_deg(__ldg(&gz.deg_t[d.y]));
        float vz = rcp_deg(__ldg(&gz.deg_t[d.z]));
        float vw = rcp_deg(__ldg(&gz.deg_t[d.w]));
        atomicAdd(&gz.a[0][s.x], vx);
        atomicAdd(&gz.a[0][s.y], vy);
        atomicAdd(&gz.a[0][s.z], vz);
        atomicAdd(&gz.a[0][s.w], vw);
    } else if (i < 2 * E4) {
        int e = i - E4;
        int4 s = __ldg(t2s + e);
        int4 d = __ldg(t2s + E4 + e);
        float vx = rcp_deg(__ldg(&gz.deg_s[d.x]));
        float vy = rcp_deg(__ldg(&gz.deg_s[d.y]));
        float vz = rcp_deg(__ldg(&gz.deg_s[d.z]));
        float vw = rcp_deg(__ldg(&gz.deg_s[d.w]));
        atomicAdd(&gz.b[0][s.x], vx);
        atomicAdd(&gz.b[0][s.y], vy);
        atomicAdd(&gz.b[0][s.z], vz);
        atomicAdd(&gz.b[0][s.w], vw);
    }
}

// ---------------- prep(r): pa = a[r]*inv_s, pb = b[r]*inv_t, + fold sums ----
__global__ void prep_kernel(int r) {
    int i = blockIdx.x * blockDim.x + threadIdx.x;
    float va = 0.0f, vb = 0.0f;
    if (i < NSRC) {
        va = gz.a[r][i];
        g_pa[i] = va * rcp_deg(gz.deg_s[i]);
    }
    if (i < NTGT) {
        vb = gz.b[r][i];
        g_pb[i] = vb * rcp_deg(gz.deg_t[i]);
    }
    #pragma unroll
    for (int off = 16; off; off >>= 1) {
        va += __shfl_down_sync(0xffffffffu, va, off);
        vb += __shfl_down_sync(0xffffffffu, vb, off);
    }
    if ((threadIdx.x & 31) == 0) {
        atomicAdd(&gz.psums[r], va);        // sum(a1)->[0], sum(a2)->[1]
        atomicAdd(&gz.psums[2 + r], vb);    // sum(b1)->[2], sum(b2)->[3]
    }
}

// ---------------- spmv_next(r): a[r][src] += pb[dst] (and mirror) -----------
__global__ void spmv_next_kernel(const int4* __restrict__ s2t,
                                 const int4* __restrict__ t2s, int r) {
    int i = blockIdx.x * blockDim.x + threadIdx.x;
    if (i < E4) {
        int4 s = __ldg(s2t + i);
        int4 d = __ldg(s2t + E4 + i);
        atomicAdd(&gz.a[r][s.x], __ldg(&g_pb[d.x]));
        atomicAdd(&gz.a[r][s.y], __ldg(&g_pb[d.y]));
        atomicAdd(&gz.a[r][s.z], __ldg(&g_pb[d.z]));
        atomicAdd(&gz.a[r][s.w], __ldg(&g_pb[d.w]));
    } else if (i < 2 * E4) {
        int e = i - E4;
        int4 s = __ldg(t2s + e);
        int4 d = __ldg(t2s + E4 + e);
        atomicAdd(&gz.b[r][s.x], __ldg(&g_pa[d.x]));
        atomicAdd(&gz.b[r][s.y], __ldg(&g_pa[d.y]));
        atomicAdd(&gz.b[r][s.z], __ldg(&g_pa[d.z]));
        atomicAdd(&gz.b[r][s.w], __ldg(&g_pa[d.w]));
    }
}

// ---------------- backward q-coefficient recursion (single block, 64 thr) ---
__global__ void qcoef_kernel(const float* __restrict__ Wl_s2t,
                             const float* __restrict__ b_s2t,
                             const float* __restrict__ Wr_s2t,
                             const float* __restrict__ Wl_t2s,
                             const float* __restrict__ b_t2s,
                             const float* __restrict__ Wr_t2s,
                             const float* __restrict__ lin_W) {
    __shared__ float QS[4][64], QT[4][64];
    __shared__ float red[64];
    int t = threadIdx.x;  // 64 threads

    float w = lin_W[t];
    #pragma unroll
    for (int k = 0; k < 4; k++) {
        QS[k][t] = (k == 0) ? w : 0.0f;
        QT[k][t] = (k == 0) ? w : 0.0f;
    }
    __syncthreads();

    float ss[4] = {(float)NSRC, gz.psums[0], gz.psums[1], 0.0f};
    float st[4] = {(float)NTGT, gz.psums[2], gz.psums[3], 0.0f};
    float acc = 0.0f;

    for (int l = 2; l >= 0; l--) {
        const float* A  = Wl_s2t + l * 4096;  // xt <- agg(xs)
        const float* B  = Wr_s2t + l * 4096;  // xt <- xt
        const float* C  = Wl_t2s + l * 4096;  // xs <- agg(xt)
        const float* Ew = Wr_t2s + l * 4096;  // xs <- xs
        float bsv = b_t2s[l * 64 + t];
        float btv = b_s2t[l * 64 + t];

        #pragma unroll
        for (int k = 0; k < 4; k++)
            acc += ss[k] * bsv * QS[k][t] + st[k] * btv * QT[k][t];

        float rs[4] = {0, 0, 0, 0}, rt[4] = {0, 0, 0, 0};
        for (int o = 0; o < 64; o++) {
            float ev = Ew[o * 64 + t];
            float av = A[o * 64 + t];
            float bv = B[o * 64 + t];
            float cv = C[o * 64 + t];
            rs[0] += ev * QS[0][o];
            rs[1] += ev * QS[1][o] + av * QT[0][o];
            rs[2] += ev * QS[2][o] + av * QT[1][o];
            rs[3] += ev * QS[3][o] + av * QT[2][o];
            rt[0] += bv * QT[0][o];
            rt[1] += bv * QT[1][o] + cv * QS[0][o];
            rt[2] += bv * QT[2][o] + cv * QS[1][o];
            rt[3] += bv * QT[3][o] + cv * QS[2][o];
        }
        __syncthreads();
        #pragma unroll
        for (int k = 0; k < 4; k++) { QS[k][t] = rs[k]; QT[k][t] = rt[k]; }
        __syncthreads();
    }

    #pragma unroll
    for (int k = 0; k < 4; k++) {
        g_Q[k][t]     = QS[k][t];
        g_Q[4 + k][t] = QT[k][t];
    }

    red[t] = acc;
    __syncthreads();
    if (t == 0) {
        float s = 0;
        #pragma unroll
        for (int i = 0; i < 64; i++) s += red[i];
        g_acc = s;
    }
}

// ---------------- final evaluation over the ORIGINAL inputs -----------------
__global__ void final_kernel(const float* __restrict__ xs,
                             const float* __restrict__ xt) {
    __shared__ float Q[8 * 64];
    __shared__ float partial[8];
    int tid = threadIdx.x;
    Q[tid] = ((const float*)g_Q)[tid];
    Q[tid + 256] = ((const float*)g_Q)[tid + 256];
    __syncthreads();

    int i = blockIdx.x * blockDim.x + tid;
    float v = 0.0f;
    if (i < NTOT) {
        bool is_s = (i < NSRC);
        int n = is_s ? i : i - NSRC;
        const float4* x = (const float4*)((is_s ? xs : xt) + (size_t)n * 64);
        const float4* Q0 = (const float4*)(Q + (is_s ? 0 : 256));
        const float4* Q1 = Q0 + 16;
        const float4* Q2 = Q0 + 32;
        const float4* Q3 = Q0 + 48;
        float c1 = is_s ? gz.a[0][n] : gz.b[0][n];
        float c2 = is_s ? gz.a[1][n] : gz.b[1][n];
        float c3 = is_s ? gz.a[2][n] : gz.b[2][n];
        #pragma unroll
        for (int j = 0; j < 16; j++) {
            float4 xv = __ldg(x + j);
            float4 q0 = Q0[j], q1 = Q1[j], q2 = Q2[j], q3 = Q3[j];
            v += xv.x * (q0.x + c1 * q1.x + c2 * q2.x + c3 * q3.x);
            v += xv.y * (q0.y + c1 * q1.y + c2 * q2.y + c3 * q3.y);
            v += xv.z * (q0.z + c1 * q1.z + c2 * q2.z + c3 * q3.z);
            v += xv.w * (q0.w + c1 * q1.w + c2 * q2.w + c3 * q3.w);
        }
    }
    #pragma unroll
    for (int off = 16; off; off >>= 1)
        v += __shfl_down_sync(0xffffffffu, v, off);
    if ((tid & 31) == 0) partial[tid >> 5] = v;
    __syncthreads();
    if (tid < 8) {
        float p = partial[tid];
        #pragma unroll
        for (int off = 4; off; off >>= 1)
            p += __shfl_down_sync(0xffu, p, off);
        if (tid == 0) atomicAdd(&gz.sum, p);
    }
}

__global__ void finalize_kernel(const float* __restrict__ lin_b,
                                float* __restrict__ out) {
    out[0] = (gz.sum + g_acc) * (1.0f / (float)NTOT) + lin_b[0];
}

// ---------------- launch ----------------------------------------------------
extern "C" void kernel_launch(void* const* d_in, const int* in_sizes, int n_in,
                              void* d_out, int out_size) {
    const float* x_source = (const float*)d_in[0];
    const float* x_target = (const float*)d_in[1];
    // d_in[2], d_in[3]: edge_attr (unused by the reference path)
    const float* W_l_s2t = (const float*)d_in[4];
    const float* b_s2t   = (const float*)d_in[5];
    const float* W_r_s2t = (const float*)d_in[6];
    const float* W_l_t2s = (const float*)d_in[7];
    const float* b_t2s   = (const float*)d_in[8];
    const float* W_r_t2s = (const float*)d_in[9];
    const float* lin_W   = (const float*)d_in[10];
    const float* lin_b   = (const float*)d_in[11];
    const int* ei_s2t    = (const int*)d_in[12];
    const int* ei_t2s    = (const int*)d_in[13];
    float* out = (float*)d_out;

    void* zb;
    cudaGetSymbolAddress(&zb, gz);
    cudaMemsetAsync(zb, 0, sizeof(ZeroBlock));   // ONE node zeroes everything

    const int4* s2t4 = (const int4*)ei_s2t;      // [0,E4): src, [E4,2E4): dst
    const int4* t2s4 = (const int4*)ei_t2s;

    const int eg = (2 * E4 + 255) / 256;         // 800K threads, 4 edges each
    const int ng = (NSRC + 255) / 256;

    deg_kernel<<<eg, 256>>>(s2t4 + E4, t2s4 + E4);
    spmv1_kernel<<<eg, 256>>>(s2t4, t2s4);            // a1, b1
    prep_kernel<<<ng, 256>>>(0);                       // pa/pb + sums(a1,b1)
    spmv_next_kernel<<<eg, 256>>>(s2t4, t2s4, 1);     // a2, b2
    prep_kernel<<<ng, 256>>>(1);                       // pa/pb + sums(a2,b2)
    spmv_next_kernel<<<eg, 256>>>(s2t4, t2s4, 2);     // a3, b3

    qcoef_kernel<<<1, 64>>>(W_l_s2t, b_s2t, W_r_s2t,
                            W_l_t2s, b_t2s, W_r_t2s, lin_W);
    final_kernel<<<(NTOT + 255) / 256, 256>>>(x_source, x_target);
    finalize_kernel<<<1, 1>>>(lin_b, out);
}

// round 6
// speedup vs baseline: 7.3236x; 1.0014x over previous
#include <cuda_runtime.h>

#define NSRC 100000
#define NTGT 100000
#define NEDGE 1600000
#define NTOT (NSRC + NTGT)
#define E4 (NEDGE / 4)

// ---------------- scratch: one contiguous zero-init block + rest ------------
struct ZeroBlock {
    int   deg_s[NSRC];
    int   deg_t[NTGT];
    float a[3][NSRC];   // a1,a2,a3 = S^T 1_t, S^T T^T 1_s, S^T T^T S^T 1_t
    float b[3][NTGT];   // b1,b2,b3 (mirror)
    float psums[4];     // sum(a1), sum(a2), sum(b1), sum(b2)
    float sum;          // final node-sum
};
__device__ ZeroBlock gz;
__device__ float g_pa[NSRC];     // a_r * inv_s (staging, fully overwritten)
__device__ float g_pb[NTGT];
__device__ float g_Q[8][64];     // level-0 coefficient vectors (fully written)
__device__ float g_acc;          // bias scalar contribution (fully written)

__device__ __forceinline__ float rcp_deg(int d) {
    return 1.0f / (float)max(d, 1);
}

// ---------------- degrees: 4 edges/thread, int4 dst loads -------------------
__global__ void deg_kernel(const int4* __restrict__ s2t_dst,
                           const int4* __restrict__ t2s_dst) {
    int i = blockIdx.x * blockDim.x + threadIdx.x;
    if (i < E4) {
        int4 d = __ldg(s2t_dst + i);
        atomicAdd(&gz.deg_t[d.x], 1);
        atomicAdd(&gz.deg_t[d.y], 1);
        atomicAdd(&gz.deg_t[d.z], 1);
        atomicAdd(&gz.deg_t[d.w], 1);
    } else if (i < 2 * E4) {
        int4 d = __ldg(t2s_dst + (i - E4));
        atomicAdd(&gz.deg_s[d.x], 1);
        atomicAdd(&gz.deg_s[d.y], 1);
        atomicAdd(&gz.deg_s[d.z], 1);
        atomicAdd(&gz.deg_s[d.w], 1);
    }
}

// ---------------- spmv1: a1[src] += rcp(deg_t[dst]) (and b1 mirror) ---------
__global__ void spmv1_kernel(const int4* __restrict__ s2t,
                             const int4* __restrict__ t2s) {
    int i = blockIdx.x * blockDim.x + threadIdx.x;
    if (i < E4) {
        int4 s = __ldg(s2t + i);
        int4 d = __ldg(s2t + E4 + i);
        float vx = rcp_deg(__ldg(&gz.deg_t[d.x]));
        float vy = rcp_deg(__ldg(&gz.deg_t[d.y]));
        float vz = rcp_deg(__ldg(&gz.deg_t[d.z]));
        float vw = rcp_deg(__ldg(&gz.deg_t[d.w]));
        atomicAdd(&gz.a[0][s.x], vx);
        atomicAdd(&gz.a[0][s.y], vy);
        atomicAdd(&gz.a[0][s.z], vz);
        atomicAdd(&gz.a[0][s.w], vw);
    } else if (i < 2 * E4) {
        int e = i - E4;
        int4 s = __ldg(t2s + e);
        int4 d = __ldg(t2s + E4 + e);
        float vx = rcp_deg(__ldg(&gz.deg_s[d.x]));
        float vy = rcp_deg(__ldg(&gz.deg_s[d.y]));
        float vz = rcp_deg(__ldg(&gz.deg_s[d.z]));
        float vw = rcp_deg(__ldg(&gz.deg_s[d.w]));
        atomicAdd(&gz.b[0][s.x], vx);
        atomicAdd(&gz.b[0][s.y], vy);
        atomicAdd(&gz.b[0][s.z], vz);
        atomicAdd(&gz.b[0][s.w], vw);
    }
}

// ---------------- prep(r): pa = a[r]*inv_s, pb = b[r]*inv_t, + fold sums ----
__global__ void prep_kernel(int r) {
    int i = blockIdx.x * blockDim.x + threadIdx.x;
    float va = 0.0f, vb = 0.0f;
    if (i < NSRC) {
        va = gz.a[r][i];
        g_pa[i] = va * rcp_deg(gz.deg_s[i]);
    }
    if (i < NTGT) {
        vb = gz.b[r][i];
        g_pb[i] = vb * rcp_deg(gz.deg_t[i]);
    }
    #pragma unroll
    for (int off = 16; off; off >>= 1) {
        va += __shfl_down_sync(0xffffffffu, va, off);
        vb += __shfl_down_sync(0xffffffffu, vb, off);
    }
    if ((threadIdx.x & 31) == 0) {
        atomicAdd(&gz.psums[r], va);        // sum(a1)->[0], sum(a2)->[1]
        atomicAdd(&gz.psums[2 + r], vb);    // sum(b1)->[2], sum(b2)->[3]
    }
}

// ---------------- spmv_next(r): a[r][src] += pb[dst] (and mirror) -----------
__global__ void spmv_next_kernel(const int4* __restrict__ s2t,
                                 const int4* __restrict__ t2s, int r) {
    int i = blockIdx.x * blockDim.x + threadIdx.x;
    if (i < E4) {
        int4 s = __ldg(s2t + i);
        int4 d = __ldg(s2t + E4 + i);
        atomicAdd(&gz.a[r][s.x], __ldg(&g_pb[d.x]));
        atomicAdd(&gz.a[r][s.y], __ldg(&g_pb[d.y]));
        atomicAdd(&gz.a[r][s.z], __ldg(&g_pb[d.z]));
        atomicAdd(&gz.a[r][s.w], __ldg(&g_pb[d.w]));
    } else if (i < 2 * E4) {
        int e = i - E4;
        int4 s = __ldg(t2s + e);
        int4 d = __ldg(t2s + E4 + e);
        atomicAdd(&gz.b[r][s.x], __ldg(&g_pa[d.x]));
        atomicAdd(&gz.b[r][s.y], __ldg(&g_pa[d.y]));
        atomicAdd(&gz.b[r][s.z], __ldg(&g_pa[d.z]));
        atomicAdd(&gz.b[r][s.w], __ldg(&g_pa[d.w]));
    }
}

// ---------------- backward q-coefficient recursion (single block, 64 thr) ---
__global__ void qcoef_kernel(const float* __restrict__ Wl_s2t,
                             const float* __restrict__ b_s2t,
                             const float* __restrict__ Wr_s2t,
                             const float* __restrict__ Wl_t2s,
                             const float* __restrict__ b_t2s,
                             const float* __restrict__ Wr_t2s,
                             const float* __restrict__ lin_W) {
    __shared__ float QS[4][64], QT[4][64];
    __shared__ float red[64];
    int t = threadIdx.x;  // 64 threads

    float w = lin_W[t];
    #pragma unroll
    for (int k = 0; k < 4; k++) {
        QS[k][t] = (k == 0) ? w : 0.0f;
        QT[k][t] = (k == 0) ? w : 0.0f;
    }
    __syncthreads();

    float ss[4] = {(float)NSRC, gz.psums[0], gz.psums[1], 0.0f};
    float st[4] = {(float)NTGT, gz.psums[2], gz.psums[3], 0.0f};
    float acc = 0.0f;

    for (int l = 2; l >= 0; l--) {
        const float* A  = Wl_s2t + l * 4096;  // xt <- agg(xs)
        const float* B  = Wr_s2t + l * 4096;  // xt <- xt
        const float* C  = Wl_t2s + l * 4096;  // xs <- agg(xt)
        const float* Ew = Wr_t2s + l * 4096;  // xs <- xs
        float bsv = b_t2s[l * 64 + t];
        float btv = b_s2t[l * 64 + t];

        #pragma unroll
        for (int k = 0; k < 4; k++)
            acc += ss[k] * bsv * QS[k][t] + st[k] * btv * QT[k][t];

        float rs[4] = {0, 0, 0, 0}, rt[4] = {0, 0, 0, 0};
        for (int o = 0; o < 64; o++) {
            float ev = Ew[o * 64 + t];
            float av = A[o * 64 + t];
            float bv = B[o * 64 + t];
            float cv = C[o * 64 + t];
            rs[0] += ev * QS[0][o];
            rs[1] += ev * QS[1][o] + av * QT[0][o];
            rs[2] += ev * QS[2][o] + av * QT[1][o];
            rs[3] += ev * QS[3][o] + av * QT[2][o];
            rt[0] += bv * QT[0][o];
            rt[1] += bv * QT[1][o] + cv * QS[0][o];
            rt[2] += bv * QT[2][o] + cv * QS[1][o];
            rt[3] += bv * QT[3][o] + cv * QS[2][o];
        }
        __syncthreads();
        #pragma unroll
        for (int k = 0; k < 4; k++) { QS[k][t] = rs[k]; QT[k][t] = rt[k]; }
        __syncthreads();
    }

    #pragma unroll
    for (int k = 0; k < 4; k++) {
        g_Q[k][t]     = QS[k][t];
        g_Q[4 + k][t] = QT[k][t];
    }

    red[t] = acc;
    __syncthreads();
    if (t == 0) {
        float s = 0;
        #pragma unroll
        for (int i = 0; i < 64; i++) s += red[i];
        g_acc = s;
    }
}

// ---------------- final evaluation over the ORIGINAL inputs -----------------
__global__ void final_kernel(const float* __restrict__ xs,
                             const float* __restrict__ xt) {
    __shared__ float Q[8 * 64];
    __shared__ float partial[8];
    int tid = threadIdx.x;
    Q[tid] = ((const float*)g_Q)[tid];
    Q[tid + 256] = ((const float*)g_Q)[tid + 256];
    __syncthreads();

    int i = blockIdx.x * blockDim.x + tid;
    float v = 0.0f;
    if (i < NTOT) {
        bool is_s = (i < NSRC);
        int n = is_s ? i : i - NSRC;
        const float4* x = (const float4*)((is_s ? xs : xt) + (size_t)n * 64);
        const float4* Q0 = (const float4*)(Q + (is_s ? 0 : 256));
        const float4* Q1 = Q0 + 16;
        const float4* Q2 = Q0 + 32;
        const float4* Q3 = Q0 + 48;
        float c1 = is_s ? gz.a[0][n] : gz.b[0][n];
        float c2 = is_s ? gz.a[1][n] : gz.b[1][n];
        float c3 = is_s ? gz.a[2][n] : gz.b[2][n];
        #pragma unroll
        for (int j = 0; j < 16; j++) {
            float4 xv = __ldg(x + j);
            float4 q0 = Q0[j], q1 = Q1[j], q2 = Q2[j], q3 = Q3[j];
            v += xv.x * (q0.x + c1 * q1.x + c2 * q2.x + c3 * q3.x);
            v += xv.y * (q0.y + c1 * q1.y + c2 * q2.y + c3 * q3.y);
            v += xv.z * (q0.z + c1 * q1.z + c2 * q2.z + c3 * q3.z);
            v += xv.w * (q0.w + c1 * q1.w + c2 * q2.w + c3 * q3.w);
        }
    }
    #pragma unroll
    for (int off = 16; off; off >>= 1)
        v += __shfl_down_sync(0xffffffffu, v, off);
    if ((tid & 31) == 0) partial[tid >> 5] = v;
    __syncthreads();
    if (tid < 8) {
        float p = partial[tid];
        #pragma unroll
        for (int off = 4; off; off >>= 1)
            p += __shfl_down_sync(0xffu, p, off);
        if (tid == 0) atomicAdd(&gz.sum, p);
    }
}

__global__ void finalize_kernel(const float* __restrict__ lin_b,
                                float* __restrict__ out) {
    out[0] = (gz.sum + g_acc) * (1.0f / (float)NTOT) + lin_b[0];
}

// ---------------- launch ----------------------------------------------------
extern "C" void kernel_launch(void* const* d_in, const int* in_sizes, int n_in,
                              void* d_out, int out_size) {
    const float* x_source = (const float*)d_in[0];
    const float* x_target = (const float*)d_in[1];
    // d_in[2], d_in[3]: edge_attr (unused by the reference path)
    const float* W_l_s2t = (const float*)d_in[4];
    const float* b_s2t   = (const float*)d_in[5];
    const float* W_r_s2t = (const float*)d_in[6];
    const float* W_l_t2s = (const float*)d_in[7];
    const float* b_t2s   = (const float*)d_in[8];
    const float* W_r_t2s = (const float*)d_in[9];
    const float* lin_W   = (const float*)d_in[10];
    const float* lin_b   = (const float*)d_in[11];
    const int* ei_s2t    = (const int*)d_in[12];
    const int* ei_t2s    = (const int*)d_in[13];
    float* out = (float*)d_out;

    void* zb;
    cudaGetSymbolAddress(&zb, gz);
    cudaMemsetAsync(zb, 0, sizeof(ZeroBlock));   // ONE node zeroes everything

    const int4* s2t4 = (const int4*)ei_s2t;      // [0,E4): src, [E4,2E4): dst
    const int4* t2s4 = (const int4*)ei_t2s;

    const int eg = (2 * E4 + 255) / 256;         // 800K threads, 4 edges each
    const int ng = (NSRC + 255) / 256;

    deg_kernel<<<eg, 256>>>(s2t4 + E4, t2s4 + E4);
    spmv1_kernel<<<eg, 256>>>(s2t4, t2s4);            // a1, b1
    prep_kernel<<<ng, 256>>>(0);                       // pa/pb + sums(a1,b1)
    spmv_next_kernel<<<eg, 256>>>(s2t4, t2s4, 1);     // a2, b2
    prep_kernel<<<ng, 256>>>(1);                       // pa/pb + sums(a2,b2)
    spmv_next_kernel<<<eg, 256>>>(s2t4, t2s4, 2);     // a3, b3

    qcoef_kernel<<<1, 64>>>(W_l_s2t, b_s2t, W_r_s2t,
                            W_l_t2s, b_t2s, W_r_t2s, lin_W);
    final_kernel<<<(NTOT + 255) / 256, 256>>>(x_source, x_target);
    finalize_kernel<<<1, 1>>>(lin_b, out);
}

// round 7
// speedup vs baseline: 7.3250x; 1.0002x over previous
#include <cuda_runtime.h>

#define NSRC 100000
#define NTGT 100000
#define NEDGE 1600000
#define NTOT (NSRC + NTGT)
#define E4 (NEDGE / 4)

// ---------------- scratch: one contiguous zero-init block + rest ------------
struct ZeroBlock {
    int   deg_s[NSRC];
    int   deg_t[NTGT];
    float a[3][NSRC];   // a1,a2,a3 = S^T 1_t, S^T T^T 1_s, S^T T^T S^T 1_t
    float b[3][NTGT];   // b1,b2,b3 (mirror)
    float psums[4];     // sum(a1), sum(a2), sum(b1), sum(b2)
    float sum;          // final node-sum
};
__device__ ZeroBlock gz;
__device__ float g_pa[NSRC];     // a_r * inv_s (staging, fully overwritten)
__device__ float g_pb[NTGT];
__device__ float g_Q[8][64];     // level-0 coefficient vectors (fully written)
__device__ float g_acc;          // bias scalar contribution (fully written)

__device__ __forceinline__ float rcp_deg(int d) {
    return 1.0f / (float)max(d, 1);
}

// ---------------- degrees: 4 edges/thread, int4 dst loads -------------------
__global__ void deg_kernel(const int4* __restrict__ s2t_dst,
                           const int4* __restrict__ t2s_dst) {
    int i = blockIdx.x * blockDim.x + threadIdx.x;
    if (i < E4) {
        int4 d = __ldg(s2t_dst + i);
        atomicAdd(&gz.deg_t[d.x], 1);
        atomicAdd(&gz.deg_t[d.y], 1);
        atomicAdd(&gz.deg_t[d.z], 1);
        atomicAdd(&gz.deg_t[d.w], 1);
    } else if (i < 2 * E4) {
        int4 d = __ldg(t2s_dst + (i - E4));
        atomicAdd(&gz.deg_s[d.x], 1);
        atomicAdd(&gz.deg_s[d.y], 1);
        atomicAdd(&gz.deg_s[d.z], 1);
        atomicAdd(&gz.deg_s[d.w], 1);
    }
}

// ---------------- spmv1: a1[src] += rcp(deg_t[dst]) (and b1 mirror) ---------
__global__ void spmv1_kernel(const int4* __restrict__ s2t,
                             const int4* __restrict__ t2s) {
    int i = blockIdx.x * blockDim.x + threadIdx.x;
    if (i < E4) {
        int4 s = __ldg(s2t + i);
        int4 d = __ldg(s2t + E4 + i);
        float vx = rcp_deg(__ldg(&gz.deg_t[d.x]));
        float vy = rcp_deg(__ldg(&gz.deg_t[d.y]));
        float vz = rcp_deg(__ldg(&gz.deg_t[d.z]));
        float vw = rcp_deg(__ldg(&gz.deg_t[d.w]));
        atomicAdd(&gz.a[0][s.x], vx);
        atomicAdd(&gz.a[0][s.y], vy);
        atomicAdd(&gz.a[0][s.z], vz);
        atomicAdd(&gz.a[0][s.w], vw);
    } else if (i < 2 * E4) {
        int e = i - E4;
        int4 s = __ldg(t2s + e);
        int4 d = __ldg(t2s + E4 + e);
        float vx = rcp_deg(__ldg(&gz.deg_s[d.x]));
        float vy = rcp_deg(__ldg(&gz.deg_s[d.y]));
        float vz = rcp_deg(__ldg(&gz.deg_s[d.z]));
        float vw = rcp_deg(__ldg(&gz.deg_s[d.w]));
        atomicAdd(&gz.b[0][s.x], vx);
        atomicAdd(&gz.b[0][s.y], vy);
        atomicAdd(&gz.b[0][s.z], vz);
        atomicAdd(&gz.b[0][s.w], vw);
    }
}

// ---------------- prep(r): pa = a[r]*inv_s, pb = b[r]*inv_t, + fold sums ----
__global__ void prep_kernel(int r) {
    int i = blockIdx.x * blockDim.x + threadIdx.x;
    float va = 0.0f, vb = 0.0f;
    if (i < NSRC) {
        va = gz.a[r][i];
        g_pa[i] = va * rcp_deg(gz.deg_s[i]);
    }
    if (i < NTGT) {
        vb = gz.b[r][i];
        g_pb[i] = vb * rcp_deg(gz.deg_t[i]);
    }
    #pragma unroll
    for (int off = 16; off; off >>= 1) {
        va += __shfl_down_sync(0xffffffffu, va, off);
        vb += __shfl_down_sync(0xffffffffu, vb, off);
    }
    if ((threadIdx.x & 31) == 0) {
        atomicAdd(&gz.psums[r], va);        // sum(a1)->[0], sum(a2)->[1]
        atomicAdd(&gz.psums[2 + r], vb);    // sum(b1)->[2], sum(b2)->[3]
    }
}

// ---------------- spmv_next(r): a[r][src] += pb[dst] (and mirror) -----------
__global__ void spmv_next_kernel(const int4* __restrict__ s2t,
                                 const int4* __restrict__ t2s, int r) {
    int i = blockIdx.x * blockDim.x + threadIdx.x;
    if (i < E4) {
        int4 s = __ldg(s2t + i);
        int4 d = __ldg(s2t + E4 + i);
        atomicAdd(&gz.a[r][s.x], __ldg(&g_pb[d.x]));
        atomicAdd(&gz.a[r][s.y], __ldg(&g_pb[d.y]));
        atomicAdd(&gz.a[r][s.z], __ldg(&g_pb[d.z]));
        atomicAdd(&gz.a[r][s.w], __ldg(&g_pb[d.w]));
    } else if (i < 2 * E4) {
        int e = i - E4;
        int4 s = __ldg(t2s + e);
        int4 d = __ldg(t2s + E4 + e);
        atomicAdd(&gz.b[r][s.x], __ldg(&g_pa[d.x]));
        atomicAdd(&gz.b[r][s.y], __ldg(&g_pa[d.y]));
        atomicAdd(&gz.b[r][s.z], __ldg(&g_pa[d.z]));
        atomicAdd(&gz.b[r][s.w], __ldg(&g_pa[d.w]));
    }
}

// ---------------- backward q-coefficient recursion (single block, 64 thr) ---
__global__ void qcoef_kernel(const float* __restrict__ Wl_s2t,
                             const float* __restrict__ b_s2t,
                             const float* __restrict__ Wr_s2t,
                             const float* __restrict__ Wl_t2s,
                             const float* __restrict__ b_t2s,
                             const float* __restrict__ Wr_t2s,
                             const float* __restrict__ lin_W) {
    __shared__ float QS[4][64], QT[4][64];
    __shared__ float red[64];
    int t = threadIdx.x;  // 64 threads

    float w = lin_W[t];
    #pragma unroll
    for (int k = 0; k < 4; k++) {
        QS[k][t] = (k == 0) ? w : 0.0f;
        QT[k][t] = (k == 0) ? w : 0.0f;
    }
    __syncthreads();

    float ss[4] = {(float)NSRC, gz.psums[0], gz.psums[1], 0.0f};
    float st[4] = {(float)NTGT, gz.psums[2], gz.psums[3], 0.0f};
    float acc = 0.0f;

    for (int l = 2; l >= 0; l--) {
        const float* A  = Wl_s2t + l * 4096;  // xt <- agg(xs)
        const float* B  = Wr_s2t + l * 4096;  // xt <- xt
        const float* C  = Wl_t2s + l * 4096;  // xs <- agg(xt)
        const float* Ew = Wr_t2s + l * 4096;  // xs <- xs
        float bsv = b_t2s[l * 64 + t];
        float btv = b_s2t[l * 64 + t];

        #pragma unroll
        for (int k = 0; k < 4; k++)
            acc += ss[k] * bsv * QS[k][t] + st[k] * btv * QT[k][t];

        float rs[4] = {0, 0, 0, 0}, rt[4] = {0, 0, 0, 0};
        for (int o = 0; o < 64; o++) {
            float ev = Ew[o * 64 + t];
            float av = A[o * 64 + t];
            float bv = B[o * 64 + t];
            float cv = C[o * 64 + t];
            rs[0] += ev * QS[0][o];
            rs[1] += ev * QS[1][o] + av * QT[0][o];
            rs[2] += ev * QS[2][o] + av * QT[1][o];
            rs[3] += ev * QS[3][o] + av * QT[2][o];
            rt[0] += bv * QT[0][o];
            rt[1] += bv * QT[1][o] + cv * QS[0][o];
            rt[2] += bv * QT[2][o] + cv * QS[1][o];
            rt[3] += bv * QT[3][o] + cv * QS[2][o];
        }
        __syncthreads();
        #pragma unroll
        for (int k = 0; k < 4; k++) { QS[k][t] = rs[k]; QT[k][t] = rt[k]; }
        __syncthreads();
    }

    #pragma unroll
    for (int k = 0; k < 4; k++) {
        g_Q[k][t]     = QS[k][t];
        g_Q[4 + k][t] = QT[k][t];
    }

    red[t] = acc;
    __syncthreads();
    if (t == 0) {
        float s = 0;
        #pragma unroll
        for (int i = 0; i < 64; i++) s += red[i];
        g_acc = s;
    }
}

// ---------------- final evaluation over the ORIGINAL inputs -----------------
__global__ void final_kernel(const float* __restrict__ xs,
                             const float* __restrict__ xt) {
    __shared__ float Q[8 * 64];
    __shared__ float partial[8];
    int tid = threadIdx.x;
    Q[tid] = ((const float*)g_Q)[tid];
    Q[tid + 256] = ((const float*)g_Q)[tid + 256];
    __syncthreads();

    int i = blockIdx.x * blockDim.x + tid;
    float v = 0.0f;
    if (i < NTOT) {
        bool is_s = (i < NSRC);
        int n = is_s ? i : i - NSRC;
        const float4* x = (const float4*)((is_s ? xs : xt) + (size_t)n * 64);
        const float4* Q0 = (const float4*)(Q + (is_s ? 0 : 256));
        const float4* Q1 = Q0 + 16;
        const float4* Q2 = Q0 + 32;
        const float4* Q3 = Q0 + 48;
        float c1 = is_s ? gz.a[0][n] : gz.b[0][n];
        float c2 = is_s ? gz.a[1][n] : gz.b[1][n];
        float c3 = is_s ? gz.a[2][n] : gz.b[2][n];
        #pragma unroll
        for (int j = 0; j < 16; j++) {
            float4 xv = __ldg(x + j);
            float4 q0 = Q0[j], q1 = Q1[j], q2 = Q2[j], q3 = Q3[j];
            v += xv.x * (q0.x + c1 * q1.x + c2 * q2.x + c3 * q3.x);
            v += xv.y * (q0.y + c1 * q1.y + c2 * q2.y + c3 * q3.y);
            v += xv.z * (q0.z + c1 * q1.z + c2 * q2.z + c3 * q3.z);
            v += xv.w * (q0.w + c1 * q1.w + c2 * q2.w + c3 * q3.w);
        }
    }
    #pragma unroll
    for (int off = 16; off; off >>= 1)
        v += __shfl_down_sync(0xffffffffu, v, off);
    if ((tid & 31) == 0) partial[tid >> 5] = v;
    __syncthreads();
    if (tid < 8) {
        float p = partial[tid];
        #pragma unroll
        for (int off = 4; off; off >>= 1)
            p += __shfl_down_sync(0xffu, p, off);
        if (tid == 0) atomicAdd(&gz.sum, p);
    }
}

__global__ void finalize_kernel(const float* __restrict__ lin_b,
                                float* __restrict__ out) {
    out[0] = (gz.sum + g_acc) * (1.0f / (float)NTOT) + lin_b[0];
}

// ---------------- launch ----------------------------------------------------
extern "C" void kernel_launch(void* const* d_in, const int* in_sizes, int n_in,
                              void* d_out, int out_size) {
    const float* x_source = (const float*)d_in[0];
    const float* x_target = (const float*)d_in[1];
    // d_in[2], d_in[3]: edge_attr (unused by the reference path)
    const float* W_l_s2t = (const float*)d_in[4];
    const float* b_s2t   = (const float*)d_in[5];
    const float* W_r_s2t = (const float*)d_in[6];
    const float* W_l_t2s = (const float*)d_in[7];
    const float* b_t2s   = (const float*)d_in[8];
    const float* W_r_t2s = (const float*)d_in[9];
    const float* lin_W   = (const float*)d_in[10];
    const float* lin_b   = (const float*)d_in[11];
    const int* ei_s2t    = (const int*)d_in[12];
    const int* ei_t2s    = (const int*)d_in[13];
    float* out = (float*)d_out;

    void* zb;
    cudaGetSymbolAddress(&zb, gz);
    cudaMemsetAsync(zb, 0, sizeof(ZeroBlock));   // ONE node zeroes everything

    const int4* s2t4 = (const int4*)ei_s2t;      // [0,E4): src, [E4,2E4): dst
    const int4* t2s4 = (const int4*)ei_t2s;

    const int eg = (2 * E4 + 255) / 256;         // 800K threads, 4 edges each
    const int ng = (NSRC + 255) / 256;

    deg_kernel<<<eg, 256>>>(s2t4 + E4, t2s4 + E4);
    spmv1_kernel<<<eg, 256>>>(s2t4, t2s4);            // a1, b1
    prep_kernel<<<ng, 256>>>(0);                       // pa/pb + sums(a1,b1)
    spmv_next_kernel<<<eg, 256>>>(s2t4, t2s4, 1);     // a2, b2
    prep_kernel<<<ng, 256>>>(1);                       // pa/pb + sums(a2,b2)
    spmv_next_kernel<<<eg, 256>>>(s2t4, t2s4, 2);     // a3, b3

    qcoef_kernel<<<1, 64>>>(W_l_s2t, b_s2t, W_r_s2t,
                            W_l_t2s, b_t2s, W_r_t2s, lin_W);
    final_kernel<<<(NTOT + 255) / 256, 256>>>(x_source, x_target);
    finalize_kernel<<<1, 1>>>(lin_b, out);
}

// round 8
// speedup vs baseline: 7.3336x; 1.0012x over previous
#include <cuda_runtime.h>

#define NSRC 100000
#define NTGT 100000
#define NEDGE 1600000
#define NTOT (NSRC + NTGT)
#define E4 (NEDGE / 4)

// ---------------- scratch: one contiguous zero-init block + rest ------------
struct ZeroBlock {
    int   deg_s[NSRC];
    int   deg_t[NTGT];
    float a[3][NSRC];   // a1,a2,a3 = S^T 1_t, S^T T^T 1_s, S^T T^T S^T 1_t
    float b[3][NTGT];   // b1,b2,b3 (mirror)
    float psums[4];     // sum(a1), sum(a2), sum(b1), sum(b2)
    float sum;          // final node-sum
};
__device__ ZeroBlock gz;
__device__ float g_pa[NSRC];     // a_r * inv_s (staging, fully overwritten)
__device__ float g_pb[NTGT];
__device__ float g_Q[8][64];     // level-0 coefficient vectors (fully written)
__device__ float g_acc;          // bias scalar contribution (fully written)

__device__ __forceinline__ float rcp_deg(int d) {
    return 1.0f / (float)max(d, 1);
}

// ---------------- degrees: 4 edges/thread, int4 dst loads -------------------
__global__ void deg_kernel(const int4* __restrict__ s2t_dst,
                           const int4* __restrict__ t2s_dst) {
    int i = blockIdx.x * blockDim.x + threadIdx.x;
    if (i < E4) {
        int4 d = __ldg(s2t_dst + i);
        atomicAdd(&gz.deg_t[d.x], 1);
        atomicAdd(&gz.deg_t[d.y], 1);
        atomicAdd(&gz.deg_t[d.z], 1);
        atomicAdd(&gz.deg_t[d.w], 1);
    } else if (i < 2 * E4) {
        int4 d = __ldg(t2s_dst + (i - E4));
        atomicAdd(&gz.deg_s[d.x], 1);
        atomicAdd(&gz.deg_s[d.y], 1);
        atomicAdd(&gz.deg_s[d.z], 1);
        atomicAdd(&gz.deg_s[d.w], 1);
    }
}

// ---------------- spmv1: a1[src] += rcp(deg_t[dst]) (and b1 mirror) ---------
__global__ void spmv1_kernel(const int4* __restrict__ s2t,
                             const int4* __restrict__ t2s) {
    int i = blockIdx.x * blockDim.x + threadIdx.x;
    if (i < E4) {
        int4 s = __ldg(s2t + i);
        int4 d = __ldg(s2t + E4 + i);
        float vx = rcp_deg(__ldg(&gz.deg_t[d.x]));
        float vy = rcp_deg(__ldg(&gz.deg_t[d.y]));
        float vz = rcp_deg(__ldg(&gz.deg_t[d.z]));
        float vw = rcp_deg(__ldg(&gz.deg_t[d.w]));
        atomicAdd(&gz.a[0][s.x], vx);
        atomicAdd(&gz.a[0][s.y], vy);
        atomicAdd(&gz.a[0][s.z], vz);
        atomicAdd(&gz.a[0][s.w], vw);
    } else if (i < 2 * E4) {
        int e = i - E4;
        int4 s = __ldg(t2s + e);
        int4 d = __ldg(t2s + E4 + e);
        float vx = rcp_deg(__ldg(&gz.deg_s[d.x]));
        float vy = rcp_deg(__ldg(&gz.deg_s[d.y]));
        float vz = rcp_deg(__ldg(&gz.deg_s[d.z]));
        float vw = rcp_deg(__ldg(&gz.deg_s[d.w]));
        atomicAdd(&gz.b[0][s.x], vx);
        atomicAdd(&gz.b[0][s.y], vy);
        atomicAdd(&gz.b[0][s.z], vz);
        atomicAdd(&gz.b[0][s.w], vw);
    }
}

// ---------------- prep(r): pa = a[r]*inv_s, pb = b[r]*inv_t, + fold sums ----
__global__ void prep_kernel(int r) {
    int i = blockIdx.x * blockDim.x + threadIdx.x;
    float va = 0.0f, vb = 0.0f;
    if (i < NSRC) {
        va = gz.a[r][i];
        g_pa[i] = va * rcp_deg(gz.deg_s[i]);
    }
    if (i < NTGT) {
        vb = gz.b[r][i];
        g_pb[i] = vb * rcp_deg(gz.deg_t[i]);
    }
    #pragma unroll
    for (int off = 16; off; off >>= 1) {
        va += __shfl_down_sync(0xffffffffu, va, off);
        vb += __shfl_down_sync(0xffffffffu, vb, off);
    }
    if ((threadIdx.x & 31) == 0) {
        atomicAdd(&gz.psums[r], va);        // sum(a1)->[0], sum(a2)->[1]
        atomicAdd(&gz.psums[2 + r], vb);    // sum(b1)->[2], sum(b2)->[3]
    }
}

// ---------------- spmv_next(r): a[r][src] += pb[dst] (and mirror) -----------
__global__ void spmv_next_kernel(const int4* __restrict__ s2t,
                                 const int4* __restrict__ t2s, int r) {
    int i = blockIdx.x * blockDim.x + threadIdx.x;
    if (i < E4) {
        int4 s = __ldg(s2t + i);
        int4 d = __ldg(s2t + E4 + i);
        atomicAdd(&gz.a[r][s.x], __ldg(&g_pb[d.x]));
        atomicAdd(&gz.a[r][s.y], __ldg(&g_pb[d.y]));
        atomicAdd(&gz.a[r][s.z], __ldg(&g_pb[d.z]));
        atomicAdd(&gz.a[r][s.w], __ldg(&g_pb[d.w]));
    } else if (i < 2 * E4) {
        int e = i - E4;
        int4 s = __ldg(t2s + e);
        int4 d = __ldg(t2s + E4 + e);
        atomicAdd(&gz.b[r][s.x], __ldg(&g_pa[d.x]));
        atomicAdd(&gz.b[r][s.y], __ldg(&g_pa[d.y]));
        atomicAdd(&gz.b[r][s.z], __ldg(&g_pa[d.z]));
        atomicAdd(&gz.b[r][s.w], __ldg(&g_pa[d.w]));
    }
}

// ---------------- backward q-coefficient recursion (single block, 64 thr) ---
__global__ void qcoef_kernel(const float* __restrict__ Wl_s2t,
                             const float* __restrict__ b_s2t,
                             const float* __restrict__ Wr_s2t,
                             const float* __restrict__ Wl_t2s,
                             const float* __restrict__ b_t2s,
                             const float* __restrict__ Wr_t2s,
                             const float* __restrict__ lin_W) {
    __shared__ float QS[4][64], QT[4][64];
    __shared__ float red[64];
    int t = threadIdx.x;  // 64 threads

    float w = lin_W[t];
    #pragma unroll
    for (int k = 0; k < 4; k++) {
        QS[k][t] = (k == 0) ? w : 0.0f;
        QT[k][t] = (k == 0) ? w : 0.0f;
    }
    __syncthreads();

    float ss[4] = {(float)NSRC, gz.psums[0], gz.psums[1], 0.0f};
    float st[4] = {(float)NTGT, gz.psums[2], gz.psums[3], 0.0f};
    float acc = 0.0f;

    for (int l = 2; l >= 0; l--) {
        const float* A  = Wl_s2t + l * 4096;  // xt <- agg(xs)
        const float* B  = Wr_s2t + l * 4096;  // xt <- xt
        const float* C  = Wl_t2s + l * 4096;  // xs <- agg(xt)
        const float* Ew = Wr_t2s + l * 4096;  // xs <- xs
        float bsv = b_t2s[l * 64 + t];
        float btv = b_s2t[l * 64 + t];

        #pragma unroll
        for (int k = 0; k < 4; k++)
            acc += ss[k] * bsv * QS[k][t] + st[k] * btv * QT[k][t];

        float rs[4] = {0, 0, 0, 0}, rt[4] = {0, 0, 0, 0};
        for (int o = 0; o < 64; o++) {
            float ev = Ew[o * 64 + t];
            float av = A[o * 64 + t];
            float bv = B[o * 64 + t];
            float cv = C[o * 64 + t];
            rs[0] += ev * QS[0][o];
            rs[1] += ev * QS[1][o] + av * QT[0][o];
            rs[2] += ev * QS[2][o] + av * QT[1][o];
            rs[3] += ev * QS[3][o] + av * QT[2][o];
            rt[0] += bv * QT[0][o];
            rt[1] += bv * QT[1][o] + cv * QS[0][o];
            rt[2] += bv * QT[2][o] + cv * QS[1][o];
            rt[3] += bv * QT[3][o] + cv * QS[2][o];
        }
        __syncthreads();
        #pragma unroll
        for (int k = 0; k < 4; k++) { QS[k][t] = rs[k]; QT[k][t] = rt[k]; }
        __syncthreads();
    }

    #pragma unroll
    for (int k = 0; k < 4; k++) {
        g_Q[k][t]     = QS[k][t];
        g_Q[4 + k][t] = QT[k][t];
    }

    red[t] = acc;
    __syncthreads();
    if (t == 0) {
        float s = 0;
        #pragma unroll
        for (int i = 0; i < 64; i++) s += red[i];
        g_acc = s;
    }
}

// ---------------- final evaluation over the ORIGINAL inputs -----------------
__global__ void final_kernel(const float* __restrict__ xs,
                             const float* __restrict__ xt) {
    __shared__ float Q[8 * 64];
    __shared__ float partial[8];
    int tid = threadIdx.x;
    Q[tid] = ((const float*)g_Q)[tid];
    Q[tid + 256] = ((const float*)g_Q)[tid + 256];
    __syncthreads();

    int i = blockIdx.x * blockDim.x + tid;
    float v = 0.0f;
    if (i < NTOT) {
        bool is_s = (i < NSRC);
        int n = is_s ? i : i - NSRC;
        const float4* x = (const float4*)((is_s ? xs : xt) + (size_t)n * 64);
        const float4* Q0 = (const float4*)(Q + (is_s ? 0 : 256));
        const float4* Q1 = Q0 + 16;
        const float4* Q2 = Q0 + 32;
        const float4* Q3 = Q0 + 48;
        float c1 = is_s ? gz.a[0][n] : gz.b[0][n];
        float c2 = is_s ? gz.a[1][n] : gz.b[1][n];
        float c3 = is_s ? gz.a[2][n] : gz.b[2][n];
        #pragma unroll
        for (int j = 0; j < 16; j++) {
            float4 xv = __ldg(x + j);
            float4 q0 = Q0[j], q1 = Q1[j], q2 = Q2[j], q3 = Q3[j];
            v += xv.x * (q0.x + c1 * q1.x + c2 * q2.x + c3 * q3.x);
            v += xv.y * (q0.y + c1 * q1.y + c2 * q2.y + c3 * q3.y);
            v += xv.z * (q0.z + c1 * q1.z + c2 * q2.z + c3 * q3.z);
            v += xv.w * (q0.w + c1 * q1.w + c2 * q2.w + c3 * q3.w);
        }
    }
    #pragma unroll
    for (int off = 16; off; off >>= 1)
        v += __shfl_down_sync(0xffffffffu, v, off);
    if ((tid & 31) == 0) partial[tid >> 5] = v;
    __syncthreads();
    if (tid < 8) {
        float p = partial[tid];
        #pragma unroll
        for (int off = 4; off; off >>= 1)
            p += __shfl_down_sync(0xffu, p, off);
        if (tid == 0) atomicAdd(&gz.sum, p);
    }
}

__global__ void finalize_kernel(const float* __restrict__ lin_b,
                                float* __restrict__ out) {
    out[0] = (gz.sum + g_acc) * (1.0f / (float)NTOT) + lin_b[0];
}

// ---------------- launch ----------------------------------------------------
extern "C" void kernel_launch(void* const* d_in, const int* in_sizes, int n_in,
                              void* d_out, int out_size) {
    const float* x_source = (const float*)d_in[0];
    const float* x_target = (const float*)d_in[1];
    // d_in[2], d_in[3]: edge_attr (unused by the reference path)
    const float* W_l_s2t = (const float*)d_in[4];
    const float* b_s2t   = (const float*)d_in[5];
    const float* W_r_s2t = (const float*)d_in[6];
    const float* W_l_t2s = (const float*)d_in[7];
    const float* b_t2s   = (const float*)d_in[8];
    const float* W_r_t2s = (const float*)d_in[9];
    const float* lin_W   = (const float*)d_in[10];
    const float* lin_b   = (const float*)d_in[11];
    const int* ei_s2t    = (const int*)d_in[12];
    const int* ei_t2s    = (const int*)d_in[13];
    float* out = (float*)d_out;

    void* zb;
    cudaGetSymbolAddress(&zb, gz);
    cudaMemsetAsync(zb, 0, sizeof(ZeroBlock));   // ONE node zeroes everything

    const int4* s2t4 = (const int4*)ei_s2t;      // [0,E4): src, [E4,2E4): dst
    const int4* t2s4 = (const int4*)ei_t2s;

    const int eg = (2 * E4 + 255) / 256;         // 800K threads, 4 edges each
    const int ng = (NSRC + 255) / 256;

    deg_kernel<<<eg, 256>>>(s2t4 + E4, t2s4 + E4);
    spmv1_kernel<<<eg, 256>>>(s2t4, t2s4);            // a1, b1
    prep_kernel<<<ng, 256>>>(0);                       // pa/pb + sums(a1,b1)
    spmv_next_kernel<<<eg, 256>>>(s2t4, t2s4, 1);     // a2, b2
    prep_kernel<<<ng, 256>>>(1);                       // pa/pb + sums(a2,b2)
    spmv_next_kernel<<<eg, 256>>>(s2t4, t2s4, 2);     // a3, b3

    qcoef_kernel<<<1, 64>>>(W_l_s2t, b_s2t, W_r_s2t,
                            W_l_t2s, b_t2s, W_r_t2s, lin_W);
    final_kernel<<<(NTOT + 255) / 256, 256>>>(x_source, x_target);
    finalize_kernel<<<1, 1>>>(lin_b, out);
}